// round 5
// baseline (speedup 1.0000x reference)
#include <cuda_runtime.h>
#include <math.h>

#define NNODES 100000
#define FIN    128
#define HID    256
#define NCLS   40
#define EMAX   1600000

// ---------------- scratch (device globals; no allocation allowed) ----------------
__device__ float g_bufA[(size_t)NNODES * HID];   // 102.4 MB
__device__ float g_bufB[(size_t)NNODES * HID];   // 102.4 MB
__device__ float g_dinv[NNODES];
__device__ int   g_hist[NNODES];
__device__ int   g_rowptr[NNODES + 1];
__device__ int   g_fill[NNODES];
__device__ int   g_col[EMAX];

__device__ __forceinline__ float* selbuf(int s) { return s ? g_bufB : g_bufA; }

// ---------------- precompute: degree, dinv, CSR by dst ----------------
__global__ void k_init() {
    int i = blockIdx.x * blockDim.x + threadIdx.x;
    if (i < NNODES) g_hist[i] = 0;
}

// edge_index is int32 (JAX x64 disabled): ei[0:E)=src, ei[E:2E)=dst
__global__ void k_hist(const int* __restrict__ ei, int E) {
    int e = blockIdx.x * blockDim.x + threadIdx.x;
    if (e < E) atomicAdd(&g_hist[ei[E + e]], 1);
}

__global__ void k_dinv() {
    int i = blockIdx.x * blockDim.x + threadIdx.x;
    if (i < NNODES) g_dinv[i] = rsqrtf((float)(g_hist[i] + 1)); // +1 self loop
}

// single-block exclusive scan of g_hist -> g_rowptr (and g_fill copy)
__global__ void k_scan(int n, int total_edges) {
    __shared__ int s[1024];
    const int t = threadIdx.x;
    const int C = (n + 1023) >> 10;
    const int lo = t * C;
    const int hi = (lo + C < n) ? lo + C : n;
    int sum = 0;
    for (int i = lo; i < hi; i++) sum += g_hist[i];
    s[t] = sum;
    __syncthreads();
    for (int off = 1; off < 1024; off <<= 1) {
        int v = (t >= off) ? s[t - off] : 0;
        __syncthreads();
        s[t] += v;
        __syncthreads();
    }
    int run = (t == 0) ? 0 : s[t - 1];
    for (int i = lo; i < hi; i++) {
        g_rowptr[i] = run;
        g_fill[i] = run;
        run += g_hist[i];
    }
    if (t == 1023) g_rowptr[n] = total_edges;
}

__global__ void k_scatter(const int* __restrict__ ei, int E) {
    int e = blockIdx.x * blockDim.x + threadIdx.x;
    if (e < E) {
        int d = ei[E + e];
        int pos = atomicAdd(&g_fill[d], 1);
        g_col[pos] = ei[e];
    }
}

// ---------------- aggregate: out[i] = dinv[i]*( sum_{s in N(i)} dinv[s]*in[s] + dinv[i]*in[i] ) ----------------
// one warp per node, 4-way unrolled neighbor loop (MLP ~8), dual accumulator banks.
template <int F, bool BIAS, bool RELU>
__global__ void k_agg(const float* __restrict__ ext_in, int src_sel, int dst_sel,
                      const float* __restrict__ bias) {
    const float* in = (src_sel < 0) ? ext_in : selbuf(src_sel);
    float* out = selbuf(dst_sel);

    const int wid = (blockIdx.x * blockDim.x + threadIdx.x) >> 5;
    if (wid >= NNODES) return;
    const int lane = threadIdx.x & 31;
    constexpr int V = F / 128;  // float4 per lane
    float4 acc0[V], acc1[V];
#pragma unroll
    for (int v = 0; v < V; v++) {
        acc0[v] = make_float4(0.f, 0.f, 0.f, 0.f);
        acc1[v] = make_float4(0.f, 0.f, 0.f, 0.f);
    }

    const int beg = g_rowptr[wid];
    const int end = g_rowptr[wid + 1];
    for (int base = beg; base < end; base += 32) {
        const int nrem = end - base;
        int idx = 0;
        float w = 0.f;
        if (lane < nrem) {
            idx = g_col[base + lane];
            w = g_dinv[idx];
        }
        const int m = nrem < 32 ? nrem : 32;
        int j = 0;
        // 4-way unrolled: 4*V independent LDG.128 in flight before any FMA use
        for (; j + 4 <= m; j += 4) {
            const int s0 = __shfl_sync(0xffffffffu, idx, j + 0);
            const int s1 = __shfl_sync(0xffffffffu, idx, j + 1);
            const int s2 = __shfl_sync(0xffffffffu, idx, j + 2);
            const int s3 = __shfl_sync(0xffffffffu, idx, j + 3);
            const float w0 = __shfl_sync(0xffffffffu, w, j + 0);
            const float w1 = __shfl_sync(0xffffffffu, w, j + 1);
            const float w2 = __shfl_sync(0xffffffffu, w, j + 2);
            const float w3 = __shfl_sync(0xffffffffu, w, j + 3);
            const float4* r0 = reinterpret_cast<const float4*>(in + (size_t)s0 * F);
            const float4* r1 = reinterpret_cast<const float4*>(in + (size_t)s1 * F);
            const float4* r2 = reinterpret_cast<const float4*>(in + (size_t)s2 * F);
            const float4* r3 = reinterpret_cast<const float4*>(in + (size_t)s3 * F);
            float4 x0[V], x1[V], x2[V], x3[V];
#pragma unroll
            for (int v = 0; v < V; v++) x0[v] = r0[lane + v * 32];
#pragma unroll
            for (int v = 0; v < V; v++) x1[v] = r1[lane + v * 32];
#pragma unroll
            for (int v = 0; v < V; v++) x2[v] = r2[lane + v * 32];
#pragma unroll
            for (int v = 0; v < V; v++) x3[v] = r3[lane + v * 32];
#pragma unroll
            for (int v = 0; v < V; v++) {
                acc0[v].x += w0 * x0[v].x; acc0[v].y += w0 * x0[v].y;
                acc0[v].z += w0 * x0[v].z; acc0[v].w += w0 * x0[v].w;
                acc1[v].x += w1 * x1[v].x; acc1[v].y += w1 * x1[v].y;
                acc1[v].z += w1 * x1[v].z; acc1[v].w += w1 * x1[v].w;
                acc0[v].x += w2 * x2[v].x; acc0[v].y += w2 * x2[v].y;
                acc0[v].z += w2 * x2[v].z; acc0[v].w += w2 * x2[v].w;
                acc1[v].x += w3 * x3[v].x; acc1[v].y += w3 * x3[v].y;
                acc1[v].z += w3 * x3[v].z; acc1[v].w += w3 * x3[v].w;
            }
        }
        for (; j < m; j++) {
            const int s = __shfl_sync(0xffffffffu, idx, j);
            const float ww = __shfl_sync(0xffffffffu, w, j);
            const float4* row = reinterpret_cast<const float4*>(in + (size_t)s * F);
#pragma unroll
            for (int v = 0; v < V; v++) {
                float4 x = row[lane + v * 32];
                acc0[v].x += ww * x.x; acc0[v].y += ww * x.y;
                acc0[v].z += ww * x.z; acc0[v].w += ww * x.w;
            }
        }
    }
    const float di = g_dinv[wid];
    const float4* self = reinterpret_cast<const float4*>(in + (size_t)wid * F);
#pragma unroll
    for (int v = 0; v < V; v++) {
        float4 x = self[lane + v * 32];
        acc0[v].x += di * x.x; acc0[v].y += di * x.y;
        acc0[v].z += di * x.z; acc0[v].w += di * x.w;
    }
    float4* orow = reinterpret_cast<float4*>(out + (size_t)wid * F);
#pragma unroll
    for (int v = 0; v < V; v++) {
        float4 r;
        r.x = di * (acc0[v].x + acc1[v].x);
        r.y = di * (acc0[v].y + acc1[v].y);
        r.z = di * (acc0[v].z + acc1[v].z);
        r.w = di * (acc0[v].w + acc1[v].w);
        if (BIAS) {
            const int c = (lane + v * 32) * 4;
            r.x += bias[c + 0]; r.y += bias[c + 1];
            r.z += bias[c + 2]; r.w += bias[c + 3];
        }
        if (RELU) {
            r.x = fmaxf(r.x, 0.f); r.y = fmaxf(r.y, 0.f);
            r.z = fmaxf(r.z, 0.f); r.w = fmaxf(r.w, 0.f);
        }
        orow[lane + v * 32] = r;
    }
}

// aggregate F=40 + bias + log_softmax (final layer), 4-way unrolled
__global__ void k_agg40_lsm(int src_sel, float* __restrict__ out,
                            const float* __restrict__ bias) {
    const float* in = selbuf(src_sel);
    const int wid = (blockIdx.x * blockDim.x + threadIdx.x) >> 5;
    if (wid >= NNODES) return;
    const int lane = threadIdx.x & 31;
    const bool has2 = lane < (NCLS - 32);

    float a0 = 0.f, a1 = 0.f, c0 = 0.f, c1 = 0.f;
    const int beg = g_rowptr[wid];
    const int end = g_rowptr[wid + 1];
    for (int base = beg; base < end; base += 32) {
        const int nrem = end - base;
        int idx = 0;
        float w = 0.f;
        if (lane < nrem) {
            idx = g_col[base + lane];
            w = g_dinv[idx];
        }
        const int m = nrem < 32 ? nrem : 32;
        int j = 0;
        for (; j + 2 <= m; j += 2) {
            const int s0 = __shfl_sync(0xffffffffu, idx, j);
            const int s1 = __shfl_sync(0xffffffffu, idx, j + 1);
            const float w0 = __shfl_sync(0xffffffffu, w, j);
            const float w1 = __shfl_sync(0xffffffffu, w, j + 1);
            const float x0 = in[(size_t)s0 * NCLS + lane];
            const float x1 = in[(size_t)s1 * NCLS + lane];
            float y0 = 0.f, y1 = 0.f;
            if (has2) { y0 = in[(size_t)s0 * NCLS + 32 + lane]; y1 = in[(size_t)s1 * NCLS + 32 + lane]; }
            a0 += w0 * x0; c0 += w1 * x1;
            if (has2) { a1 += w0 * y0; c1 += w1 * y1; }
        }
        for (; j < m; j++) {
            const int s = __shfl_sync(0xffffffffu, idx, j);
            const float ww = __shfl_sync(0xffffffffu, w, j);
            a0 += ww * in[(size_t)s * NCLS + lane];
            if (has2) a1 += ww * in[(size_t)s * NCLS + 32 + lane];
        }
    }
    a0 += c0; a1 += c1;
    const float di = g_dinv[wid];
    a0 += di * in[(size_t)wid * NCLS + lane];
    if (has2) a1 += di * in[(size_t)wid * NCLS + 32 + lane];

    a0 = di * a0 + bias[lane];
    a1 = has2 ? (di * a1 + bias[32 + lane]) : -INFINITY;

    float mx = fmaxf(a0, a1);
#pragma unroll
    for (int off = 16; off; off >>= 1) mx = fmaxf(mx, __shfl_xor_sync(0xffffffffu, mx, off));
    float se = expf(a0 - mx) + (has2 ? expf(a1 - mx) : 0.f);
#pragma unroll
    for (int off = 16; off; off >>= 1) se += __shfl_xor_sync(0xffffffffu, se, off);
    const float lse = logf(se) + mx;

    out[(size_t)wid * NCLS + lane] = a0 - lse;
    if (has2) out[(size_t)wid * NCLS + 32 + lane] = a1 - lse;
}

// ---------------- big fp32 GEMM: 128x128x16 tiles, 8x8 microtile, double-buffered ----------------
template <int K, int NOUT, bool EPI>
__global__ __launch_bounds__(256, 2) void k_gemm2(int src_sel, const float* __restrict__ W,
                                                  const float* __restrict__ bias, int dst_sel) {
    const float* A = selbuf(src_sel);
    float* C = selbuf(dst_sel);

    constexpr int BM = 128, BN = 128, BK = 16;
    constexpr int T = K / BK;
    __shared__ float As[2][BK][BM + 4];
    __shared__ float Bs[2][BK][BN];

    const int tid = threadIdx.x;
    const int tx = tid & 15;
    const int ty = tid >> 4;
    const int m0 = blockIdx.x * BM;
    const int n0 = blockIdx.y * BN;

    float acc[8][8];
#pragma unroll
    for (int i = 0; i < 8; i++)
#pragma unroll
        for (int j = 0; j < 8; j++) acc[i][j] = 0.f;

    float4 ra[2], rb[2];

    auto load_regs = [&](int t) {
#pragma unroll
        for (int l = 0; l < 2; l++) {
            const int lin = tid + l * 256;
            const int r = lin >> 2;
            const int c4 = lin & 3;
            const int gr = m0 + r;
            ra[l] = make_float4(0.f, 0.f, 0.f, 0.f);
            if (gr < NNODES)
                ra[l] = *reinterpret_cast<const float4*>(A + (size_t)gr * K + t * BK + c4 * 4);
            const int br = lin >> 5;
            const int bc4 = lin & 31;
            rb[l] = *reinterpret_cast<const float4*>(W + (size_t)(t * BK + br) * NOUT + n0 + bc4 * 4);
        }
    };
    auto store_smem = [&](int buf) {
#pragma unroll
        for (int l = 0; l < 2; l++) {
            const int lin = tid + l * 256;
            const int r = lin >> 2;
            const int c4 = lin & 3;
            As[buf][c4 * 4 + 0][r] = ra[l].x;
            As[buf][c4 * 4 + 1][r] = ra[l].y;
            As[buf][c4 * 4 + 2][r] = ra[l].z;
            As[buf][c4 * 4 + 3][r] = ra[l].w;
            const int br = lin >> 5;
            const int bc4 = lin & 31;
            *reinterpret_cast<float4*>(&Bs[buf][br][bc4 * 4]) = rb[l];
        }
    };

    load_regs(0);
    store_smem(0);
    __syncthreads();

    for (int t = 0; t < T; t++) {
        const int cur = t & 1;
        if (t + 1 < T) load_regs(t + 1);
#pragma unroll
        for (int kk = 0; kk < BK; kk++) {
            float a[8], b[8];
            *reinterpret_cast<float4*>(&a[0]) = *reinterpret_cast<const float4*>(&As[cur][kk][ty * 8]);
            *reinterpret_cast<float4*>(&a[4]) = *reinterpret_cast<const float4*>(&As[cur][kk][ty * 8 + 4]);
            *reinterpret_cast<float4*>(&b[0]) = *reinterpret_cast<const float4*>(&Bs[cur][kk][tx * 8]);
            *reinterpret_cast<float4*>(&b[4]) = *reinterpret_cast<const float4*>(&Bs[cur][kk][tx * 8 + 4]);
#pragma unroll
            for (int i = 0; i < 8; i++)
#pragma unroll
                for (int j = 0; j < 8; j++) acc[i][j] += a[i] * b[j];
        }
        if (t + 1 < T) {
            store_smem((t + 1) & 1);
            __syncthreads();
        }
    }

    float bz[8];
#pragma unroll
    for (int j = 0; j < 8; j++) bz[j] = EPI ? bias[n0 + tx * 8 + j] : 0.f;
#pragma unroll
    for (int i = 0; i < 8; i++) {
        const int m = m0 + ty * 8 + i;
        if (m >= NNODES) continue;
        float4 r0, r1;
        r0.x = acc[i][0]; r0.y = acc[i][1]; r0.z = acc[i][2]; r0.w = acc[i][3];
        r1.x = acc[i][4]; r1.y = acc[i][5]; r1.z = acc[i][6]; r1.w = acc[i][7];
        if (EPI) {
            r0.x = fmaxf(r0.x + bz[0], 0.f); r0.y = fmaxf(r0.y + bz[1], 0.f);
            r0.z = fmaxf(r0.z + bz[2], 0.f); r0.w = fmaxf(r0.w + bz[3], 0.f);
            r1.x = fmaxf(r1.x + bz[4], 0.f); r1.y = fmaxf(r1.y + bz[5], 0.f);
            r1.z = fmaxf(r1.z + bz[6], 0.f); r1.w = fmaxf(r1.w + bz[7], 0.f);
        }
        float* crow = C + (size_t)m * NOUT + n0 + tx * 8;
        *reinterpret_cast<float4*>(crow) = r0;
        *reinterpret_cast<float4*>(crow + 4) = r1;
    }
}

// ---------------- small GEMM for NOUT=40 ----------------
template <int K, int NOUT>
__global__ void k_gemm_small(int src_sel, const float* __restrict__ W, int dst_sel) {
    const float* A = selbuf(src_sel);
    float* C = selbuf(dst_sel);

    constexpr int BM = 128, BN = 64, BK = 32;
    __shared__ float As[BK][BM];
    __shared__ float Bs[BK][BN];
    const int tid = threadIdx.x;
    const int tx = tid & 15;
    const int ty = tid >> 4;
    const int m0 = blockIdx.x * BM;
    const int n0 = blockIdx.y * BN;

    float acc[8][4];
#pragma unroll
    for (int i = 0; i < 8; i++)
#pragma unroll
        for (int j = 0; j < 4; j++) acc[i][j] = 0.f;

    for (int k0 = 0; k0 < K; k0 += BK) {
#pragma unroll
        for (int l = 0; l < 4; l++) {
            const int lin = tid + l * 256;
            const int r = lin >> 3;
            const int c4 = lin & 7;
            float4 v = make_float4(0.f, 0.f, 0.f, 0.f);
            const int gr = m0 + r;
            if (gr < NNODES)
                v = *reinterpret_cast<const float4*>(A + (size_t)gr * K + k0 + c4 * 4);
            As[c4 * 4 + 0][r] = v.x;
            As[c4 * 4 + 1][r] = v.y;
            As[c4 * 4 + 2][r] = v.z;
            As[c4 * 4 + 3][r] = v.w;
        }
#pragma unroll
        for (int l = 0; l < 2; l++) {
            const int lin = tid + l * 256;
            const int r = lin >> 4;
            const int c4 = lin & 15;
            float4 v = make_float4(0.f, 0.f, 0.f, 0.f);
            const int gc = n0 + c4 * 4;
            if (gc < NOUT)
                v = *reinterpret_cast<const float4*>(W + (size_t)(k0 + r) * NOUT + gc);
            *reinterpret_cast<float4*>(&Bs[r][c4 * 4]) = v;
        }
        __syncthreads();
#pragma unroll
        for (int kk = 0; kk < BK; kk++) {
            float a[8];
#pragma unroll
            for (int i = 0; i < 8; i++) a[i] = As[kk][ty * 8 + i];
            const float4 b = *reinterpret_cast<const float4*>(&Bs[kk][tx * 4]);
            const float bb[4] = {b.x, b.y, b.z, b.w};
#pragma unroll
            for (int i = 0; i < 8; i++)
#pragma unroll
                for (int j = 0; j < 4; j++) acc[i][j] += a[i] * bb[j];
        }
        __syncthreads();
    }

#pragma unroll
    for (int i = 0; i < 8; i++) {
        const int m = m0 + ty * 8 + i;
        if (m >= NNODES) continue;
#pragma unroll
        for (int j = 0; j < 4; j++) {
            const int c = n0 + tx * 4 + j;
            if (c >= NOUT) continue;
            C[(size_t)m * NOUT + c] = acc[i][j];
        }
    }
}

// ---------------- launch ----------------
extern "C" void kernel_launch(void* const* d_in, const int* in_sizes, int n_in,
                              void* d_out, int out_size) {
    const float* x = (const float*)d_in[0];
    const int* ei = (const int*)d_in[1];   // int32 (JAX x64 disabled)
    const float* W1 = (const float*)d_in[2];
    const float* b1 = (const float*)d_in[3];
    const float* W2 = (const float*)d_in[4];
    const float* b2 = (const float*)d_in[5];
    const float* W3 = (const float*)d_in[6];
    const float* b3 = (const float*)d_in[7];
    const float* W4 = (const float*)d_in[8];
    const float* b4 = (const float*)d_in[9];
    float* out = (float*)d_out;
    const int E = in_sizes[1] / 2;

    // graph structure precompute
    k_init<<<(NNODES + 255) / 256, 256>>>();
    k_hist<<<(E + 255) / 256, 256>>>(ei, E);
    k_scan<<<1, 1024>>>(NNODES, E);
    k_dinv<<<(NNODES + 255) / 256, 256>>>();
    k_scatter<<<(E + 255) / 256, 256>>>(ei, E);

    const int AGG_BLOCKS = (NNODES + 7) / 8;  // 8 warps/block
    const dim3 G2((NNODES + 127) / 128, HID / 128);
    const dim3 G5((NNODES + 127) / 128, 1);

    // conv1: aggregate (F=128), then GEMM + bias + relu
    k_agg<128, false, false><<<AGG_BLOCKS, 256>>>(x, -1, 0, nullptr);        // x -> A
    k_gemm2<128, 256, true><<<G2, 256>>>(0, W1, b1, 1);                      // A -> B

    // conv2: GEMM, then aggregate + bias + relu
    k_gemm2<256, 256, false><<<G2, 256>>>(1, W2, nullptr, 0);                // B -> A
    k_agg<256, true, true><<<AGG_BLOCKS, 256>>>(nullptr, 0, 1, b2);          // A -> B

    // conv3 (reuses W2/b2)
    k_gemm2<256, 256, false><<<G2, 256>>>(1, W2, nullptr, 0);
    k_agg<256, true, true><<<AGG_BLOCKS, 256>>>(nullptr, 0, 1, b2);

    // conv4
    k_gemm2<256, 256, false><<<G2, 256>>>(1, W3, nullptr, 0);
    k_agg<256, true, true><<<AGG_BLOCKS, 256>>>(nullptr, 0, 1, b3);

    // conv5: GEMM to 40 classes, aggregate + bias + log_softmax
    k_gemm_small<256, 40><<<G5, 256>>>(1, W4, 0);
    k_agg40_lsm<<<AGG_BLOCKS, 256>>>(0, out, b4);
}

// round 6
// speedup vs baseline: 1.2336x; 1.2336x over previous
#include <cuda_runtime.h>
#include <cuda_fp16.h>
#include <math.h>

#define NNODES 100000
#define FIN    128
#define HID    256
#define NCLS   40
#define EMAX   1600000

// ---------------- scratch (device globals; no allocation allowed) ----------------
__device__ __half g_bufA[(size_t)NNODES * HID];   // 51.2 MB
__device__ __half g_bufB[(size_t)NNODES * HID];   // 51.2 MB
__device__ float g_dinv[NNODES];
__device__ int   g_hist[NNODES];
__device__ int   g_rowptr[NNODES + 1];
__device__ int   g_fill[NNODES];
__device__ int   g_col[EMAX];

__device__ __forceinline__ __half* selbuf(int s) { return s ? g_bufB : g_bufA; }

__device__ __forceinline__ void h8_to_f8(uint4 v, float* f) {
    const __half2* h = reinterpret_cast<const __half2*>(&v);
#pragma unroll
    for (int k = 0; k < 4; k++) {
        float2 t = __half22float2(h[k]);
        f[2 * k] = t.x;
        f[2 * k + 1] = t.y;
    }
}
__device__ __forceinline__ uint4 f8_to_h8(const float* f) {
    uint4 o;
    __half2* h = reinterpret_cast<__half2*>(&o);
#pragma unroll
    for (int k = 0; k < 4; k++) h[k] = __floats2half2_rn(f[2 * k], f[2 * k + 1]);
    return o;
}

// ---------------- precompute: degree, dinv, CSR by dst ----------------
__global__ void k_init() {
    int i = blockIdx.x * blockDim.x + threadIdx.x;
    if (i < NNODES) g_hist[i] = 0;
}

// edge_index is int32 (JAX x64 disabled): ei[0:E)=src, ei[E:2E)=dst
__global__ void k_hist(const int* __restrict__ ei, int E) {
    int e = blockIdx.x * blockDim.x + threadIdx.x;
    if (e < E) atomicAdd(&g_hist[ei[E + e]], 1);
}

__global__ void k_dinv() {
    int i = blockIdx.x * blockDim.x + threadIdx.x;
    if (i < NNODES) g_dinv[i] = rsqrtf((float)(g_hist[i] + 1)); // +1 self loop
}

__global__ void k_scan(int n, int total_edges) {
    __shared__ int s[1024];
    const int t = threadIdx.x;
    const int C = (n + 1023) >> 10;
    const int lo = t * C;
    const int hi = (lo + C < n) ? lo + C : n;
    int sum = 0;
    for (int i = lo; i < hi; i++) sum += g_hist[i];
    s[t] = sum;
    __syncthreads();
    for (int off = 1; off < 1024; off <<= 1) {
        int v = (t >= off) ? s[t - off] : 0;
        __syncthreads();
        s[t] += v;
        __syncthreads();
    }
    int run = (t == 0) ? 0 : s[t - 1];
    for (int i = lo; i < hi; i++) {
        g_rowptr[i] = run;
        g_fill[i] = run;
        run += g_hist[i];
    }
    if (t == 1023) g_rowptr[n] = total_edges;
}

__global__ void k_scatter(const int* __restrict__ ei, int E) {
    int e = blockIdx.x * blockDim.x + threadIdx.x;
    if (e < E) {
        int d = ei[E + e];
        int pos = atomicAdd(&g_fill[d], 1);
        g_col[pos] = ei[e];
    }
}

// ---------------- agg conv1: gather fp32 x (F=128), write half ----------------
__global__ void k_agg_x(const float* __restrict__ in, int dst_sel) {
    __half* out = selbuf(dst_sel);
    const int wid = (blockIdx.x * blockDim.x + threadIdx.x) >> 5;
    if (wid >= NNODES) return;
    const int lane = threadIdx.x & 31;

    float4 acc = make_float4(0.f, 0.f, 0.f, 0.f);
    const int beg = g_rowptr[wid];
    const int end = g_rowptr[wid + 1];
    for (int base = beg; base < end; base += 32) {
        const int nrem = end - base;
        int idx = 0;
        float w = 0.f;
        if (lane < nrem) {
            idx = g_col[base + lane];
            w = g_dinv[idx];
        }
        const int m = nrem < 32 ? nrem : 32;
        int j = 0;
        for (; j + 2 <= m; j += 2) {
            const int s0 = __shfl_sync(0xffffffffu, idx, j);
            const int s1 = __shfl_sync(0xffffffffu, idx, j + 1);
            const float w0 = __shfl_sync(0xffffffffu, w, j);
            const float w1 = __shfl_sync(0xffffffffu, w, j + 1);
            float4 x0 = reinterpret_cast<const float4*>(in + (size_t)s0 * FIN)[lane];
            float4 x1 = reinterpret_cast<const float4*>(in + (size_t)s1 * FIN)[lane];
            acc.x += w0 * x0.x + w1 * x1.x;
            acc.y += w0 * x0.y + w1 * x1.y;
            acc.z += w0 * x0.z + w1 * x1.z;
            acc.w += w0 * x0.w + w1 * x1.w;
        }
        for (; j < m; j++) {
            const int s = __shfl_sync(0xffffffffu, idx, j);
            const float ww = __shfl_sync(0xffffffffu, w, j);
            float4 x = reinterpret_cast<const float4*>(in + (size_t)s * FIN)[lane];
            acc.x += ww * x.x; acc.y += ww * x.y;
            acc.z += ww * x.z; acc.w += ww * x.w;
        }
    }
    const float di = g_dinv[wid];
    float4 x = reinterpret_cast<const float4*>(in + (size_t)wid * FIN)[lane];
    acc.x = di * (acc.x + di * x.x);
    acc.y = di * (acc.y + di * x.y);
    acc.z = di * (acc.z + di * x.z);
    acc.w = di * (acc.w + di * x.w);

    uint2 o;
    __half2* oh = reinterpret_cast<__half2*>(&o);
    oh[0] = __floats2half2_rn(acc.x, acc.y);
    oh[1] = __floats2half2_rn(acc.z, acc.w);
    *reinterpret_cast<uint2*>(out + (size_t)wid * FIN + lane * 4) = o;
}

// ---------------- agg mid layers: gather half F=256, +bias+relu, write half ----------------
__global__ void k_agg_h256(int src_sel, int dst_sel, const float* __restrict__ bias) {
    const __half* in = selbuf(src_sel);
    __half* out = selbuf(dst_sel);
    const int wid = (blockIdx.x * blockDim.x + threadIdx.x) >> 5;
    if (wid >= NNODES) return;
    const int lane = threadIdx.x & 31;
    const int coff = lane * 8;  // 8 halfs per lane

    float acc[8];
#pragma unroll
    for (int i = 0; i < 8; i++) acc[i] = 0.f;

    const int beg = g_rowptr[wid];
    const int end = g_rowptr[wid + 1];
    for (int base = beg; base < end; base += 32) {
        const int nrem = end - base;
        int idx = 0;
        float w = 0.f;
        if (lane < nrem) {
            idx = g_col[base + lane];
            w = g_dinv[idx];
        }
        const int m = nrem < 32 ? nrem : 32;
        int j = 0;
        for (; j + 2 <= m; j += 2) {
            const int s0 = __shfl_sync(0xffffffffu, idx, j);
            const int s1 = __shfl_sync(0xffffffffu, idx, j + 1);
            const float w0 = __shfl_sync(0xffffffffu, w, j);
            const float w1 = __shfl_sync(0xffffffffu, w, j + 1);
            uint4 v0 = *reinterpret_cast<const uint4*>(in + (size_t)s0 * HID + coff);
            uint4 v1 = *reinterpret_cast<const uint4*>(in + (size_t)s1 * HID + coff);
            float f0[8], f1[8];
            h8_to_f8(v0, f0);
            h8_to_f8(v1, f1);
#pragma unroll
            for (int i = 0; i < 8; i++) acc[i] += w0 * f0[i] + w1 * f1[i];
        }
        for (; j < m; j++) {
            const int s = __shfl_sync(0xffffffffu, idx, j);
            const float ww = __shfl_sync(0xffffffffu, w, j);
            uint4 v = *reinterpret_cast<const uint4*>(in + (size_t)s * HID + coff);
            float f[8];
            h8_to_f8(v, f);
#pragma unroll
            for (int i = 0; i < 8; i++) acc[i] += ww * f[i];
        }
    }
    const float di = g_dinv[wid];
    {
        uint4 v = *reinterpret_cast<const uint4*>(in + (size_t)wid * HID + coff);
        float f[8];
        h8_to_f8(v, f);
#pragma unroll
        for (int i = 0; i < 8; i++) acc[i] += di * f[i];
    }
    float r[8];
#pragma unroll
    for (int i = 0; i < 8; i++) {
        r[i] = fmaxf(di * acc[i] + bias[coff + i], 0.f);
    }
    *reinterpret_cast<uint4*>(out + (size_t)wid * HID + coff) = f8_to_h8(r);
}

// ---------------- final: gather half F=40, +bias, log_softmax, write fp32 ----------------
__global__ void k_agg40_lsm(int src_sel, float* __restrict__ out,
                            const float* __restrict__ bias) {
    const __half* in = selbuf(src_sel);
    const int wid = (blockIdx.x * blockDim.x + threadIdx.x) >> 5;
    if (wid >= NNODES) return;
    const int lane = threadIdx.x & 31;
    const bool has2 = lane < (NCLS - 32);

    float a0 = 0.f, a1 = 0.f;
    const int beg = g_rowptr[wid];
    const int end = g_rowptr[wid + 1];
    for (int base = beg; base < end; base += 32) {
        const int nrem = end - base;
        int idx = 0;
        float w = 0.f;
        if (lane < nrem) {
            idx = g_col[base + lane];
            w = g_dinv[idx];
        }
        const int m = nrem < 32 ? nrem : 32;
        for (int j = 0; j < m; j++) {
            const int s = __shfl_sync(0xffffffffu, idx, j);
            const float ww = __shfl_sync(0xffffffffu, w, j);
            a0 += ww * __half2float(in[(size_t)s * NCLS + lane]);
            if (has2) a1 += ww * __half2float(in[(size_t)s * NCLS + 32 + lane]);
        }
    }
    const float di = g_dinv[wid];
    a0 += di * __half2float(in[(size_t)wid * NCLS + lane]);
    if (has2) a1 += di * __half2float(in[(size_t)wid * NCLS + 32 + lane]);

    a0 = di * a0 + bias[lane];
    a1 = has2 ? (di * a1 + bias[32 + lane]) : -INFINITY;

    float mx = fmaxf(a0, a1);
#pragma unroll
    for (int off = 16; off; off >>= 1) mx = fmaxf(mx, __shfl_xor_sync(0xffffffffu, mx, off));
    float se = expf(a0 - mx) + (has2 ? expf(a1 - mx) : 0.f);
#pragma unroll
    for (int off = 16; off; off >>= 1) se += __shfl_xor_sync(0xffffffffu, se, off);
    const float lse = logf(se) + mx;

    out[(size_t)wid * NCLS + lane] = a0 - lse;
    if (has2) out[(size_t)wid * NCLS + 32 + lane] = a1 - lse;
}

// ---------------- GEMM: C_half[M,256] = A_half[M,K] @ W_f32[K,256] (+bias+relu) ----------------
// 128x128x16 tiles, 8x8 microtile, double-buffered smem, fp32 accumulate.
template <int K, bool EPI>
__global__ __launch_bounds__(256, 2) void k_gemm_h(int src_sel, const float* __restrict__ W,
                                                   const float* __restrict__ bias, int dst_sel) {
    const __half* A = selbuf(src_sel);
    __half* C = selbuf(dst_sel);
    constexpr int NOUT = HID;
    constexpr int BM = 128, BN = 128, BK = 16;
    constexpr int T = K / BK;
    __shared__ float As[2][BK][BM + 4];
    __shared__ float Bs[2][BK][BN];

    const int tid = threadIdx.x;
    const int tx = tid & 15;
    const int ty = tid >> 4;
    const int m0 = blockIdx.x * BM;
    const int n0 = blockIdx.y * BN;

    // A mapping: tid -> row r=tid>>1 (0..127), k-chunk c8=tid&1 (halfs [c8*8, c8*8+8))
    const int Ar = tid >> 1;
    const int Ac8 = tid & 1;

    float acc[8][8];
#pragma unroll
    for (int i = 0; i < 8; i++)
#pragma unroll
        for (int j = 0; j < 8; j++) acc[i][j] = 0.f;

    uint4 ra;
    float4 rb[2];

    auto load_regs = [&](int t) {
        const int gr = m0 + Ar;
        ra = make_uint4(0, 0, 0, 0);
        if (gr < NNODES)
            ra = *reinterpret_cast<const uint4*>(A + (size_t)gr * K + t * BK + Ac8 * 8);
#pragma unroll
        for (int l = 0; l < 2; l++) {
            const int lin = tid + l * 256;
            const int br = lin >> 5;
            const int bc4 = lin & 31;
            rb[l] = *reinterpret_cast<const float4*>(W + (size_t)(t * BK + br) * NOUT + n0 + bc4 * 4);
        }
    };
    auto store_smem = [&](int buf) {
        float f[8];
        h8_to_f8(ra, f);
#pragma unroll
        for (int i = 0; i < 8; i++) As[buf][Ac8 * 8 + i][Ar] = f[i];
#pragma unroll
        for (int l = 0; l < 2; l++) {
            const int lin = tid + l * 256;
            const int br = lin >> 5;
            const int bc4 = lin & 31;
            *reinterpret_cast<float4*>(&Bs[buf][br][bc4 * 4]) = rb[l];
        }
    };

    load_regs(0);
    store_smem(0);
    __syncthreads();

    for (int t = 0; t < T; t++) {
        const int cur = t & 1;
        if (t + 1 < T) load_regs(t + 1);
#pragma unroll
        for (int kk = 0; kk < BK; kk++) {
            float a[8], b[8];
            *reinterpret_cast<float4*>(&a[0]) = *reinterpret_cast<const float4*>(&As[cur][kk][ty * 8]);
            *reinterpret_cast<float4*>(&a[4]) = *reinterpret_cast<const float4*>(&As[cur][kk][ty * 8 + 4]);
            *reinterpret_cast<float4*>(&b[0]) = *reinterpret_cast<const float4*>(&Bs[cur][kk][tx * 8]);
            *reinterpret_cast<float4*>(&b[4]) = *reinterpret_cast<const float4*>(&Bs[cur][kk][tx * 8 + 4]);
#pragma unroll
            for (int i = 0; i < 8; i++)
#pragma unroll
                for (int j = 0; j < 8; j++) acc[i][j] += a[i] * b[j];
        }
        if (t + 1 < T) {
            store_smem((t + 1) & 1);
            __syncthreads();
        }
    }

    float bz[8];
#pragma unroll
    for (int j = 0; j < 8; j++) bz[j] = EPI ? bias[n0 + tx * 8 + j] : 0.f;
#pragma unroll
    for (int i = 0; i < 8; i++) {
        const int m = m0 + ty * 8 + i;
        if (m >= NNODES) continue;
        float r[8];
#pragma unroll
        for (int j = 0; j < 8; j++) {
            r[j] = acc[i][j];
            if (EPI) r[j] = fmaxf(r[j] + bz[j], 0.f);
        }
        *reinterpret_cast<uint4*>(C + (size_t)m * NOUT + n0 + tx * 8) = f8_to_h8(r);
    }
}

// ---------------- small GEMM: C_half[M,40] = A_half[M,256] @ W_f32[256,40] ----------------
__global__ void k_gemm_small(int src_sel, const float* __restrict__ W, int dst_sel) {
    const __half* A = selbuf(src_sel);
    __half* C = selbuf(dst_sel);
    constexpr int K = HID, NOUT = NCLS;
    constexpr int BM = 128, BN = 64, BK = 32;
    __shared__ float As[BK][BM];
    __shared__ float Bs[BK][BN];
    const int tid = threadIdx.x;
    const int tx = tid & 15;
    const int ty = tid >> 4;
    const int m0 = blockIdx.x * BM;

    float acc[8][4];
#pragma unroll
    for (int i = 0; i < 8; i++)
#pragma unroll
        for (int j = 0; j < 4; j++) acc[i][j] = 0.f;

    for (int k0 = 0; k0 < K; k0 += BK) {
        // A tile 128x32 halfs: 512 uint4 loads, 2 per thread
#pragma unroll
        for (int l = 0; l < 2; l++) {
            const int lin = tid + l * 256;
            const int r = lin >> 2;
            const int c8 = lin & 3;
            uint4 v = make_uint4(0, 0, 0, 0);
            const int gr = m0 + r;
            if (gr < NNODES)
                v = *reinterpret_cast<const uint4*>(A + (size_t)gr * K + k0 + c8 * 8);
            float f[8];
            h8_to_f8(v, f);
#pragma unroll
            for (int i = 0; i < 8; i++) As[c8 * 8 + i][r] = f[i];
        }
        // B tile 32x40 (padded to 64): 2 float4 per thread with col guard
#pragma unroll
        for (int l = 0; l < 2; l++) {
            const int lin = tid + l * 256;
            const int r = lin >> 4;
            const int c4 = lin & 15;
            float4 v = make_float4(0.f, 0.f, 0.f, 0.f);
            const int gc = c4 * 4;
            if (gc < NOUT)
                v = *reinterpret_cast<const float4*>(W + (size_t)(k0 + r) * NOUT + gc);
            *reinterpret_cast<float4*>(&Bs[r][c4 * 4]) = v;
        }
        __syncthreads();
#pragma unroll
        for (int kk = 0; kk < BK; kk++) {
            float a[8];
#pragma unroll
            for (int i = 0; i < 8; i++) a[i] = As[kk][ty * 8 + i];
            const float4 b = *reinterpret_cast<const float4*>(&Bs[kk][tx * 4]);
            const float bb[4] = {b.x, b.y, b.z, b.w};
#pragma unroll
            for (int i = 0; i < 8; i++)
#pragma unroll
                for (int j = 0; j < 4; j++) acc[i][j] += a[i] * bb[j];
        }
        __syncthreads();
    }

#pragma unroll
    for (int i = 0; i < 8; i++) {
        const int m = m0 + ty * 8 + i;
        if (m >= NNODES) continue;
        const int c0 = tx * 4;
        if (c0 + 3 < NOUT) {
            uint2 o;
            __half2* oh = reinterpret_cast<__half2*>(&o);
            oh[0] = __floats2half2_rn(acc[i][0], acc[i][1]);
            oh[1] = __floats2half2_rn(acc[i][2], acc[i][3]);
            *reinterpret_cast<uint2*>(C + (size_t)m * NOUT + c0) = o;
        }
    }
}

// ---------------- launch ----------------
extern "C" void kernel_launch(void* const* d_in, const int* in_sizes, int n_in,
                              void* d_out, int out_size) {
    const float* x = (const float*)d_in[0];
    const int* ei = (const int*)d_in[1];   // int32 (JAX x64 disabled)
    const float* W1 = (const float*)d_in[2];
    const float* b1 = (const float*)d_in[3];
    const float* W2 = (const float*)d_in[4];
    const float* b2 = (const float*)d_in[5];
    const float* W3 = (const float*)d_in[6];
    const float* b3 = (const float*)d_in[7];
    const float* W4 = (const float*)d_in[8];
    const float* b4 = (const float*)d_in[9];
    float* out = (float*)d_out;
    const int E = in_sizes[1] / 2;

    // graph structure precompute
    k_init<<<(NNODES + 255) / 256, 256>>>();
    k_hist<<<(E + 255) / 256, 256>>>(ei, E);
    k_scan<<<1, 1024>>>(NNODES, E);
    k_dinv<<<(NNODES + 255) / 256, 256>>>();
    k_scatter<<<(E + 255) / 256, 256>>>(ei, E);

    const int AGG_BLOCKS = (NNODES + 7) / 8;  // 8 warps/block
    const dim3 G2((NNODES + 127) / 128, HID / 128);
    const dim3 G5((NNODES + 127) / 128, 1);

    // conv1: aggregate x (fp32 in, fp16 out), then GEMM + bias + relu
    k_agg_x<<<AGG_BLOCKS, 256>>>(x, 0);                        // x -> A
    k_gemm_h<128, true><<<G2, 256>>>(0, W1, b1, 1);            // A -> B

    // conv2
    k_gemm_h<256, false><<<G2, 256>>>(1, W2, nullptr, 0);      // B -> A
    k_agg_h256<<<AGG_BLOCKS, 256>>>(0, 1, b2);                 // A -> B

    // conv3 (reuses W2/b2)
    k_gemm_h<256, false><<<G2, 256>>>(1, W2, nullptr, 0);
    k_agg_h256<<<AGG_BLOCKS, 256>>>(0, 1, b2);

    // conv4
    k_gemm_h<256, false><<<G2, 256>>>(1, W3, nullptr, 0);
    k_agg_h256<<<AGG_BLOCKS, 256>>>(0, 1, b3);

    // conv5: GEMM to 40 classes, aggregate + bias + log_softmax
    k_gemm_small<<<G5, 256>>>(1, W4, 0);                       // B -> A
    k_agg40_lsm<<<AGG_BLOCKS, 256>>>(0, out, b4);
}

// round 7
// speedup vs baseline: 1.9430x; 1.5751x over previous
#include <cuda_runtime.h>
#include <cuda_fp16.h>
#include <math.h>

#define NNODES 100000
#define NPAD   100096   // 782 blocks * 128 rows
#define FIN    128
#define HID    256
#define NCLS   40
#define EMAX   1600000

// ---------------- scratch (device globals; no allocation allowed) ----------------
__device__ __half g_bufA[(size_t)NPAD * HID];   // 51.2 MB (pad rows stay zero)
__device__ __half g_bufB[(size_t)NPAD * HID];   // 51.2 MB
__device__ __half g_W1T[256 * 128];             // transposed+permuted fp16 weights
__device__ __half g_W2T[256 * 256];
__device__ __half g_W3T[256 * 256];
__device__ float g_dinv[NNODES];
__device__ int   g_hist[NNODES];
__device__ int   g_rowptr[NNODES + 1];
__device__ int   g_fill[NNODES];
__device__ int   g_col[EMAX];

__device__ __forceinline__ __half* selbuf(int s) { return s ? g_bufB : g_bufA; }

__device__ __forceinline__ void h8_to_f8(uint4 v, float* f) {
    const __half2* h = reinterpret_cast<const __half2*>(&v);
#pragma unroll
    for (int k = 0; k < 4; k++) {
        float2 t = __half22float2(h[k]);
        f[2 * k] = t.x;
        f[2 * k + 1] = t.y;
    }
}
__device__ __forceinline__ uint4 f8_to_h8(const float* f) {
    uint4 o;
    __half2* h = reinterpret_cast<__half2*>(&o);
#pragma unroll
    for (int k = 0; k < 4; k++) h[k] = __floats2half2_rn(f[2 * k], f[2 * k + 1]);
    return o;
}

// ---------------- precompute: degree, dinv, CSR by dst ----------------
__global__ void k_init() {
    int i = blockIdx.x * blockDim.x + threadIdx.x;
    if (i < NNODES) g_hist[i] = 0;
}

__global__ void k_hist(const int* __restrict__ ei, int E) {
    int e = blockIdx.x * blockDim.x + threadIdx.x;
    if (e < E) atomicAdd(&g_hist[ei[E + e]], 1);
}

__global__ void k_dinv() {
    int i = blockIdx.x * blockDim.x + threadIdx.x;
    if (i < NNODES) g_dinv[i] = rsqrtf((float)(g_hist[i] + 1));
}

__global__ void k_scan(int n, int total_edges) {
    __shared__ int s[1024];
    const int t = threadIdx.x;
    const int C = (n + 1023) >> 10;
    const int lo = t * C;
    const int hi = (lo + C < n) ? lo + C : n;
    int sum = 0;
    for (int i = lo; i < hi; i++) sum += g_hist[i];
    s[t] = sum;
    __syncthreads();
    for (int off = 1; off < 1024; off <<= 1) {
        int v = (t >= off) ? s[t - off] : 0;
        __syncthreads();
        s[t] += v;
        __syncthreads();
    }
    int run = (t == 0) ? 0 : s[t - 1];
    for (int i = lo; i < hi; i++) {
        g_rowptr[i] = run;
        g_fill[i] = run;
        run += g_hist[i];
    }
    if (t == 1023) g_rowptr[n] = total_edges;
}

__global__ void k_scatter(const int* __restrict__ ei, int E) {
    int e = blockIdx.x * blockDim.x + threadIdx.x;
    if (e < E) {
        int d = ei[E + e];
        int pos = atomicAdd(&g_fill[d], 1);
        g_col[pos] = ei[e];
    }
}

// ---------------- weight conversion: fp32 [K,256] -> fp16 WT[n][k], k-permuted per 16-group ----------------
// perm: stored position p in 16-group holds original k = 2*((p>>2)&3) + (p&1) + ((p>>1)&1)*8
__global__ void k_wconv(const float* __restrict__ W1, const float* __restrict__ W2,
                        const float* __restrict__ W3) {
    int i = blockIdx.x * blockDim.x + threadIdx.x;
    if (i < 256 * 256) {
        int n = i >> 8, k = i & 255;
        int ko = (k & ~15) + 2 * ((k >> 2) & 3) + (k & 1) + (((k >> 1) & 1) << 3);
        g_W2T[n * 256 + k] = __float2half(W2[ko * 256 + n]);
        g_W3T[n * 256 + k] = __float2half(W3[ko * 256 + n]);
    }
    if (i < 256 * 128) {
        int n = i >> 7, k = i & 127;
        int ko = (k & ~15) + 2 * ((k >> 2) & 3) + (k & 1) + (((k >> 1) & 1) << 3);
        g_W1T[n * 128 + k] = __float2half(W1[ko * 256 + n]);
    }
}

// ---------------- agg conv1: gather fp32 x (F=128), write half ----------------
__global__ void k_agg_x(const float* __restrict__ in, int dst_sel) {
    __half* out = selbuf(dst_sel);
    const int wid = (blockIdx.x * blockDim.x + threadIdx.x) >> 5;
    if (wid >= NNODES) return;
    const int lane = threadIdx.x & 31;

    float4 acc = make_float4(0.f, 0.f, 0.f, 0.f);
    const int beg = g_rowptr[wid];
    const int end = g_rowptr[wid + 1];
    for (int base = beg; base < end; base += 32) {
        const int nrem = end - base;
        int idx = 0;
        float w = 0.f;
        if (lane < nrem) {
            idx = g_col[base + lane];
            w = g_dinv[idx];
        }
        const int m = nrem < 32 ? nrem : 32;
        int j = 0;
        for (; j + 2 <= m; j += 2) {
            const int s0 = __shfl_sync(0xffffffffu, idx, j);
            const int s1 = __shfl_sync(0xffffffffu, idx, j + 1);
            const float w0 = __shfl_sync(0xffffffffu, w, j);
            const float w1 = __shfl_sync(0xffffffffu, w, j + 1);
            float4 x0 = reinterpret_cast<const float4*>(in + (size_t)s0 * FIN)[lane];
            float4 x1 = reinterpret_cast<const float4*>(in + (size_t)s1 * FIN)[lane];
            acc.x += w0 * x0.x + w1 * x1.x;
            acc.y += w0 * x0.y + w1 * x1.y;
            acc.z += w0 * x0.z + w1 * x1.z;
            acc.w += w0 * x0.w + w1 * x1.w;
        }
        for (; j < m; j++) {
            const int s = __shfl_sync(0xffffffffu, idx, j);
            const float ww = __shfl_sync(0xffffffffu, w, j);
            float4 x = reinterpret_cast<const float4*>(in + (size_t)s * FIN)[lane];
            acc.x += ww * x.x; acc.y += ww * x.y;
            acc.z += ww * x.z; acc.w += ww * x.w;
        }
    }
    const float di = g_dinv[wid];
    float4 x = reinterpret_cast<const float4*>(in + (size_t)wid * FIN)[lane];
    acc.x = di * (acc.x + di * x.x);
    acc.y = di * (acc.y + di * x.y);
    acc.z = di * (acc.z + di * x.z);
    acc.w = di * (acc.w + di * x.w);

    uint2 o;
    __half2* oh = reinterpret_cast<__half2*>(&o);
    oh[0] = __floats2half2_rn(acc.x, acc.y);
    oh[1] = __floats2half2_rn(acc.z, acc.w);
    *reinterpret_cast<uint2*>(out + (size_t)wid * FIN + lane * 4) = o;
}

// ---------------- agg mid layers: gather half F=256, +bias+relu, write half ----------------
__global__ void k_agg_h256(int src_sel, int dst_sel, const float* __restrict__ bias) {
    const __half* in = selbuf(src_sel);
    __half* out = selbuf(dst_sel);
    const int wid = (blockIdx.x * blockDim.x + threadIdx.x) >> 5;
    if (wid >= NNODES) return;
    const int lane = threadIdx.x & 31;
    const int coff = lane * 8;

    float acc[8];
#pragma unroll
    for (int i = 0; i < 8; i++) acc[i] = 0.f;

    const int beg = g_rowptr[wid];
    const int end = g_rowptr[wid + 1];
    for (int base = beg; base < end; base += 32) {
        const int nrem = end - base;
        int idx = 0;
        float w = 0.f;
        if (lane < nrem) {
            idx = g_col[base + lane];
            w = g_dinv[idx];
        }
        const int m = nrem < 32 ? nrem : 32;
        int j = 0;
        for (; j + 2 <= m; j += 2) {
            const int s0 = __shfl_sync(0xffffffffu, idx, j);
            const int s1 = __shfl_sync(0xffffffffu, idx, j + 1);
            const float w0 = __shfl_sync(0xffffffffu, w, j);
            const float w1 = __shfl_sync(0xffffffffu, w, j + 1);
            uint4 v0 = *reinterpret_cast<const uint4*>(in + (size_t)s0 * HID + coff);
            uint4 v1 = *reinterpret_cast<const uint4*>(in + (size_t)s1 * HID + coff);
            float f0[8], f1[8];
            h8_to_f8(v0, f0);
            h8_to_f8(v1, f1);
#pragma unroll
            for (int i = 0; i < 8; i++) acc[i] += w0 * f0[i] + w1 * f1[i];
        }
        for (; j < m; j++) {
            const int s = __shfl_sync(0xffffffffu, idx, j);
            const float ww = __shfl_sync(0xffffffffu, w, j);
            uint4 v = *reinterpret_cast<const uint4*>(in + (size_t)s * HID + coff);
            float f[8];
            h8_to_f8(v, f);
#pragma unroll
            for (int i = 0; i < 8; i++) acc[i] += ww * f[i];
        }
    }
    const float di = g_dinv[wid];
    {
        uint4 v = *reinterpret_cast<const uint4*>(in + (size_t)wid * HID + coff);
        float f[8];
        h8_to_f8(v, f);
#pragma unroll
        for (int i = 0; i < 8; i++) acc[i] += di * f[i];
    }
    float r[8];
#pragma unroll
    for (int i = 0; i < 8; i++) {
        r[i] = fmaxf(di * acc[i] + bias[coff + i], 0.f);
    }
    *reinterpret_cast<uint4*>(out + (size_t)wid * HID + coff) = f8_to_h8(r);
}

// ---------------- final: gather half F=40, +bias, log_softmax, write fp32 ----------------
__global__ void k_agg40_lsm(int src_sel, float* __restrict__ out,
                            const float* __restrict__ bias) {
    const __half* in = selbuf(src_sel);
    const int wid = (blockIdx.x * blockDim.x + threadIdx.x) >> 5;
    if (wid >= NNODES) return;
    const int lane = threadIdx.x & 31;
    const bool has2 = lane < (NCLS - 32);

    float a0 = 0.f, a1 = 0.f;
    const int beg = g_rowptr[wid];
    const int end = g_rowptr[wid + 1];
    for (int base = beg; base < end; base += 32) {
        const int nrem = end - base;
        int idx = 0;
        float w = 0.f;
        if (lane < nrem) {
            idx = g_col[base + lane];
            w = g_dinv[idx];
        }
        const int m = nrem < 32 ? nrem : 32;
        for (int j = 0; j < m; j++) {
            const int s = __shfl_sync(0xffffffffu, idx, j);
            const float ww = __shfl_sync(0xffffffffu, w, j);
            a0 += ww * __half2float(in[(size_t)s * NCLS + lane]);
            if (has2) a1 += ww * __half2float(in[(size_t)s * NCLS + 32 + lane]);
        }
    }
    const float di = g_dinv[wid];
    a0 += di * __half2float(in[(size_t)wid * NCLS + lane]);
    if (has2) a1 += di * __half2float(in[(size_t)wid * NCLS + 32 + lane]);

    a0 = di * a0 + bias[lane];
    a1 = has2 ? (di * a1 + bias[32 + lane]) : -INFINITY;

    float mx = fmaxf(a0, a1);
#pragma unroll
    for (int off = 16; off; off >>= 1) mx = fmaxf(mx, __shfl_xor_sync(0xffffffffu, mx, off));
    float se = expf(a0 - mx) + (has2 ? expf(a1 - mx) : 0.f);
#pragma unroll
    for (int off = 16; off; off >>= 1) se += __shfl_xor_sync(0xffffffffu, se, off);
    const float lse = logf(se) + mx;

    out[(size_t)wid * NCLS + lane] = a0 - lse;
    if (has2) out[(size_t)wid * NCLS + 32 + lane] = a1 - lse;
}

// ---------------- tensor-core GEMM: C_half[M,256] = A_half[M,K] @ W[K,256] ----------------
// HMMA mma.sync.m16n8k16, fp32 accum. 128x128 block, 8 warps (4 M x 2 N), warp = 32x64.
// No smem: A frags via LDG.32 (L1/L2 resident), B frags via single LDG.64 from permuted WT.
template <int K, bool EPI>
__global__ __launch_bounds__(256) void k_gemm_mma(int src_sel, int wsel,
                                                  const float* __restrict__ bias, int dst_sel) {
    const __half* A = selbuf(src_sel);
    __half* C = selbuf(dst_sel);
    const __half* WT = (wsel == 1) ? g_W1T : (wsel == 2) ? g_W2T : g_W3T;

    const int tid = threadIdx.x;
    const int wid = tid >> 5;
    const int lane = tid & 31;
    const int gid = lane >> 2;   // 0..7
    const int tig = lane & 3;    // 0..3
    const int mbase = blockIdx.x * 128 + (wid & 3) * 32;
    const int nbase = blockIdx.y * 128 + (wid >> 2) * 64;

    float c[2][8][4];
#pragma unroll
    for (int i = 0; i < 2; i++)
#pragma unroll
        for (int j = 0; j < 8; j++)
#pragma unroll
            for (int q = 0; q < 4; q++) c[i][j][q] = 0.f;

#pragma unroll 4
    for (int kg = 0; kg < K / 16; kg++) {
        const int k0 = kg * 16;
        unsigned a[2][4];
#pragma unroll
        for (int i = 0; i < 2; i++) {
            const __half* ap = A + (size_t)(mbase + i * 16 + gid) * K + k0 + 2 * tig;
            a[i][0] = *reinterpret_cast<const unsigned*>(ap);
            a[i][1] = *reinterpret_cast<const unsigned*>(ap + 8 * K);
            a[i][2] = *reinterpret_cast<const unsigned*>(ap + 8);
            a[i][3] = *reinterpret_cast<const unsigned*>(ap + 8 * K + 8);
        }
#pragma unroll
        for (int j = 0; j < 8; j++) {
            const uint2 b = *reinterpret_cast<const uint2*>(
                WT + (size_t)(nbase + j * 8 + gid) * K + k0 + tig * 4);
#pragma unroll
            for (int i = 0; i < 2; i++) {
                asm volatile(
                    "mma.sync.aligned.m16n8k16.row.col.f32.f16.f16.f32 "
                    "{%0,%1,%2,%3}, {%4,%5,%6,%7}, {%8,%9}, {%0,%1,%2,%3};"
                    : "+f"(c[i][j][0]), "+f"(c[i][j][1]), "+f"(c[i][j][2]), "+f"(c[i][j][3])
                    : "r"(a[i][0]), "r"(a[i][1]), "r"(a[i][2]), "r"(a[i][3]),
                      "r"(b.x), "r"(b.y));
            }
        }
    }

#pragma unroll
    for (int i = 0; i < 2; i++) {
        const int r0 = mbase + i * 16 + gid;
#pragma unroll
        for (int j = 0; j < 8; j++) {
            const int col = nbase + j * 8 + 2 * tig;
            float v0 = c[i][j][0], v1 = c[i][j][1], v2 = c[i][j][2], v3 = c[i][j][3];
            if (EPI) {
                const float bz0 = bias[col];
                const float bz1 = bias[col + 1];
                v0 = fmaxf(v0 + bz0, 0.f); v1 = fmaxf(v1 + bz1, 0.f);
                v2 = fmaxf(v2 + bz0, 0.f); v3 = fmaxf(v3 + bz1, 0.f);
            }
            if (r0 < NNODES)
                *reinterpret_cast<__half2*>(C + (size_t)r0 * HID + col) = __floats2half2_rn(v0, v1);
            if (r0 + 8 < NNODES)
                *reinterpret_cast<__half2*>(C + (size_t)(r0 + 8) * HID + col) = __floats2half2_rn(v2, v3);
        }
    }
}

// ---------------- small GEMM: C_half[M,40] = A_half[M,256] @ W_f32[256,40] ----------------
__global__ void k_gemm_small(int src_sel, const float* __restrict__ W, int dst_sel) {
    const __half* A = selbuf(src_sel);
    __half* C = selbuf(dst_sel);
    constexpr int K = HID, NOUT = NCLS;
    constexpr int BM = 128, BN = 64, BK = 32;
    __shared__ float As[BK][BM];
    __shared__ float Bs[BK][BN];
    const int tid = threadIdx.x;
    const int tx = tid & 15;
    const int ty = tid >> 4;
    const int m0 = blockIdx.x * BM;

    float acc[8][4];
#pragma unroll
    for (int i = 0; i < 8; i++)
#pragma unroll
        for (int j = 0; j < 4; j++) acc[i][j] = 0.f;

    for (int k0 = 0; k0 < K; k0 += BK) {
#pragma unroll
        for (int l = 0; l < 2; l++) {
            const int lin = tid + l * 256;
            const int r = lin >> 2;
            const int c8 = lin & 3;
            uint4 v = make_uint4(0, 0, 0, 0);
            const int gr = m0 + r;
            if (gr < NNODES)
                v = *reinterpret_cast<const uint4*>(A + (size_t)gr * K + k0 + c8 * 8);
            float f[8];
            h8_to_f8(v, f);
#pragma unroll
            for (int i = 0; i < 8; i++) As[c8 * 8 + i][r] = f[i];
        }
#pragma unroll
        for (int l = 0; l < 2; l++) {
            const int lin = tid + l * 256;
            const int r = lin >> 4;
            const int c4 = lin & 15;
            float4 v = make_float4(0.f, 0.f, 0.f, 0.f);
            const int gc = c4 * 4;
            if (gc < NOUT)
                v = *reinterpret_cast<const float4*>(W + (size_t)(k0 + r) * NOUT + gc);
            *reinterpret_cast<float4*>(&Bs[r][c4 * 4]) = v;
        }
        __syncthreads();
#pragma unroll
        for (int kk = 0; kk < BK; kk++) {
            float a[8];
#pragma unroll
            for (int i = 0; i < 8; i++) a[i] = As[kk][ty * 8 + i];
            const float4 b = *reinterpret_cast<const float4*>(&Bs[kk][tx * 4]);
            const float bb[4] = {b.x, b.y, b.z, b.w};
#pragma unroll
            for (int i = 0; i < 8; i++)
#pragma unroll
                for (int j = 0; j < 4; j++) acc[i][j] += a[i] * bb[j];
        }
        __syncthreads();
    }

#pragma unroll
    for (int i = 0; i < 8; i++) {
        const int m = m0 + ty * 8 + i;
        if (m >= NNODES) continue;
        const int c0 = tx * 4;
        if (c0 + 3 < NOUT) {
            uint2 o;
            __half2* oh = reinterpret_cast<__half2*>(&o);
            oh[0] = __floats2half2_rn(acc[i][0], acc[i][1]);
            oh[1] = __floats2half2_rn(acc[i][2], acc[i][3]);
            *reinterpret_cast<uint2*>(C + (size_t)m * NOUT + c0) = o;
        }
    }
}

// ---------------- launch ----------------
extern "C" void kernel_launch(void* const* d_in, const int* in_sizes, int n_in,
                              void* d_out, int out_size) {
    const float* x = (const float*)d_in[0];
    const int* ei = (const int*)d_in[1];   // int32 (JAX x64 disabled)
    const float* W1 = (const float*)d_in[2];
    const float* b1 = (const float*)d_in[3];
    const float* W2 = (const float*)d_in[4];
    const float* b2 = (const float*)d_in[5];
    const float* W3 = (const float*)d_in[6];
    const float* b3 = (const float*)d_in[7];
    const float* W4 = (const float*)d_in[8];
    const float* b4 = (const float*)d_in[9];
    float* out = (float*)d_out;
    const int E = in_sizes[1] / 2;

    // graph structure + weight precompute
    k_init<<<(NNODES + 255) / 256, 256>>>();
    k_hist<<<(E + 255) / 256, 256>>>(ei, E);
    k_scan<<<1, 1024>>>(NNODES, E);
    k_dinv<<<(NNODES + 255) / 256, 256>>>();
    k_scatter<<<(E + 255) / 256, 256>>>(ei, E);
    k_wconv<<<(256 * 256 + 255) / 256, 256>>>(W1, W2, W3);

    const int AGG_BLOCKS = (NNODES + 7) / 8;
    const dim3 GM((NNODES + 127) / 128, 2);   // 128x128 tiles over N=256
    const dim3 G5((NNODES + 127) / 128, 1);

    // conv1: aggregate x (fp32 in, fp16 out), then tensor-core GEMM + bias + relu
    k_agg_x<<<AGG_BLOCKS, 256>>>(x, 0);                         // x -> A
    k_gemm_mma<128, true><<<GM, 256>>>(0, 1, b1, 1);            // A -> B

    // conv2
    k_gemm_mma<256, false><<<GM, 256>>>(1, 2, nullptr, 0);      // B -> A
    k_agg_h256<<<AGG_BLOCKS, 256>>>(0, 1, b2);                  // A -> B

    // conv3 (reuses W2/b2)
    k_gemm_mma<256, false><<<GM, 256>>>(1, 2, nullptr, 0);
    k_agg_h256<<<AGG_BLOCKS, 256>>>(0, 1, b2);

    // conv4
    k_gemm_mma<256, false><<<GM, 256>>>(1, 3, nullptr, 0);
    k_agg_h256<<<AGG_BLOCKS, 256>>>(0, 1, b3);

    // conv5: GEMM to 40 classes, aggregate + bias + log_softmax
    k_gemm_small<<<G5, 256>>>(1, W4, 0);                        // B -> A
    k_agg40_lsm<<<AGG_BLOCKS, 256>>>(0, out, b4);
}